// round 1
// baseline (speedup 1.0000x reference)
#include <cuda_runtime.h>
#include <math.h>

#define Bn 2
#define Dn 1024
#define Tn 2048
#define Hn 16
#define DHn 64

// scratch for projected Q, K, V laid out as [b*H+h][t][dh]
__device__ float g_q[(size_t)Bn * Hn * Tn * DHn];
__device__ float g_k[(size_t)Bn * Hn * Tn * DHn];
__device__ float g_v[(size_t)Bn * Hn * Tn * DHn];

// XOR swizzle for stride-64 smem tiles: float4 group g of row r lives at group (g ^ (r&15))
__device__ __forceinline__ int sw4(int r, int g) {
    return r * 64 + ((g ^ (r & 15)) << 2);
}
__device__ __forceinline__ int sw1(int r, int c) {
    return r * 64 + ((((c >> 2) ^ (r & 15)) << 2) | (c & 3));
}

// ---------------------------------------------------------------------------
// Kernel 1: fused QKV projection.
// C[t, dh] = sum_d x[b, d, t] * w[n, h, d, dh]   per (n, b, h)
// grid = (T/64, 3*B*H), block = 256, thread tile 4x4
// ---------------------------------------------------------------------------
__global__ __launch_bounds__(256) void qkv_proj_kernel(const float* __restrict__ x,
                                                       const float* __restrict__ w) {
    __shared__ float Xs[16][68];
    __shared__ float Ws[16][68];

    const int tid = threadIdx.x;
    const int tx = tid & 15, ty = tid >> 4;
    const int t0 = blockIdx.x * 64;
    const int nbh = blockIdx.y;          // n*32 + b*16 + h
    const int n = nbh >> 5;
    const int b = (nbh >> 4) & 1;
    const int h = nbh & 15;

    const float* xp = x + ((size_t)b * Dn) * Tn + t0;           // + d*T + t_local
    const float* wp = w + (size_t)(n * Hn + h) * Dn * DHn;      // + d*64 + dh

    const int lr = tid >> 6;   // 0..3
    const int lc = tid & 63;   // 0..63

    float acc[4][4] = {};

    for (int k0 = 0; k0 < Dn; k0 += 16) {
        #pragma unroll
        for (int u = 0; u < 4; u++) {
            int r = lr + u * 4;
            Xs[r][lc] = xp[(size_t)(k0 + r) * Tn + lc];
            Ws[r][lc] = wp[(size_t)(k0 + r) * DHn + lc];
        }
        __syncthreads();
        #pragma unroll
        for (int kd = 0; kd < 16; kd++) {
            float4 a4 = *(const float4*)&Xs[kd][ty * 4];
            float4 b4 = *(const float4*)&Ws[kd][tx * 4];
            float a[4] = {a4.x, a4.y, a4.z, a4.w};
            float bb[4] = {b4.x, b4.y, b4.z, b4.w};
            #pragma unroll
            for (int i = 0; i < 4; i++)
                #pragma unroll
                for (int j = 0; j < 4; j++)
                    acc[i][j] += a[i] * bb[j];
        }
        __syncthreads();
    }

    float* outp = (n == 0 ? g_q : (n == 1 ? g_k : g_v))
                + ((size_t)(b * Hn + h) * Tn + t0) * DHn;
    #pragma unroll
    for (int i = 0; i < 4; i++) {
        float4 v4 = make_float4(acc[i][0], acc[i][1], acc[i][2], acc[i][3]);
        *(float4*)&outp[(size_t)(ty * 4 + i) * DHn + tx * 4] = v4;
    }
}

// ---------------------------------------------------------------------------
// Kernel 2: flash attention per (b,h), 64 queries per block, streaming over
// 64-key tiles with online softmax. smem = Q(16K) + K/P(16K) + V(16K) = 48KB.
// Output written as out[b, h*64+dh, t] (coalesced via smem transpose).
// ---------------------------------------------------------------------------
__global__ __launch_bounds__(256) void attn_kernel(float* __restrict__ out) {
    __shared__ float Qs[64 * 64];
    __shared__ float Ks[64 * 64];   // reused as P after scores are computed
    __shared__ float Vs[64 * 64];

    const int tid = threadIdx.x;
    const int tx = tid & 15, ty = tid >> 4;
    const int t0 = blockIdx.x * 64;
    const int bh = blockIdx.y;      // b*16 + h
    const int lr = tid >> 6, lc = tid & 63;

    const float* qp = g_q + ((size_t)bh * Tn + t0) * DHn;
    const float* kb = g_k + (size_t)bh * Tn * DHn;
    const float* vb = g_v + (size_t)bh * Tn * DHn;

    // stage Q tile (pre-scaled by 1/sqrt(Dh) = 0.125)
    #pragma unroll
    for (int u = 0; u < 16; u++) {
        int r = lr + u * 4;
        Qs[sw1(r, lc)] = qp[(size_t)r * DHn + lc] * 0.125f;
    }

    float m[4], l[4], o[4][4];
    #pragma unroll
    for (int i = 0; i < 4; i++) {
        m[i] = -1e30f; l[i] = 0.f;
        #pragma unroll
        for (int j = 0; j < 4; j++) o[i][j] = 0.f;
    }

    #pragma unroll 1
    for (int kt = 0; kt < Tn / 64; kt++) {
        const float* kp = kb + (size_t)kt * 64 * DHn;
        const float* vp = vb + (size_t)kt * 64 * DHn;

        __syncthreads();   // prior O-GEMM done reading K(P)/V; Q visible on iter 0
        #pragma unroll
        for (int u = 0; u < 16; u++) {
            int r = lr + u * 4;
            Ks[sw1(r, lc)] = kp[(size_t)r * DHn + lc];
            Vs[sw1(r, lc)] = vp[(size_t)r * DHn + lc];
        }
        __syncthreads();

        // S[q=ty*4+i][k=tx+16j] = Q . K
        float s[4][4] = {};
        #pragma unroll
        for (int d4 = 0; d4 < 16; d4++) {
            float4 qv[4], kv[4];
            #pragma unroll
            for (int i = 0; i < 4; i++) qv[i] = *(const float4*)&Qs[sw4(ty * 4 + i, d4)];
            #pragma unroll
            for (int j = 0; j < 4; j++) kv[j] = *(const float4*)&Ks[sw4(tx + 16 * j, d4)];
            #pragma unroll
            for (int i = 0; i < 4; i++)
                #pragma unroll
                for (int j = 0; j < 4; j++)
                    s[i][j] += qv[i].x * kv[j].x + qv[i].y * kv[j].y
                             + qv[i].z * kv[j].z + qv[i].w * kv[j].w;
        }

        // online softmax: each row q is owned by the 16 lanes sharing ty
        #pragma unroll
        for (int i = 0; i < 4; i++) {
            float tmax = fmaxf(fmaxf(s[i][0], s[i][1]), fmaxf(s[i][2], s[i][3]));
            #pragma unroll
            for (int off = 8; off > 0; off >>= 1)
                tmax = fmaxf(tmax, __shfl_xor_sync(0xffffffffu, tmax, off));
            float mnew = fmaxf(m[i], tmax);
            float corr = __expf(m[i] - mnew);
            float rs = 0.f;
            #pragma unroll
            for (int j = 0; j < 4; j++) { s[i][j] = __expf(s[i][j] - mnew); rs += s[i][j]; }
            #pragma unroll
            for (int off = 8; off > 0; off >>= 1)
                rs += __shfl_xor_sync(0xffffffffu, rs, off);
            l[i] = l[i] * corr + rs;
            m[i] = mnew;
            #pragma unroll
            for (int j = 0; j < 4; j++) o[i][j] *= corr;
        }

        __syncthreads();   // all lanes finished reading Ks before P overwrites it
        #pragma unroll
        for (int i = 0; i < 4; i++)
            #pragma unroll
            for (int j = 0; j < 4; j++)
                Ks[sw1(ty * 4 + i, tx + 16 * j)] = s[i][j];
        __syncthreads();

        // O[q=ty*4+i][dh=tx*4+j] += P . V
        #pragma unroll
        for (int k4 = 0; k4 < 16; k4++) {
            float4 pv[4], vv[4];
            #pragma unroll
            for (int i = 0; i < 4; i++) pv[i] = *(const float4*)&Ks[sw4(ty * 4 + i, k4)];
            #pragma unroll
            for (int kk = 0; kk < 4; kk++) vv[kk] = *(const float4*)&Vs[sw4(k4 * 4 + kk, tx)];
            #pragma unroll
            for (int i = 0; i < 4; i++) {
                o[i][0] += pv[i].x * vv[0].x + pv[i].y * vv[1].x + pv[i].z * vv[2].x + pv[i].w * vv[3].x;
                o[i][1] += pv[i].x * vv[0].y + pv[i].y * vv[1].y + pv[i].z * vv[2].y + pv[i].w * vv[3].y;
                o[i][2] += pv[i].x * vv[0].z + pv[i].y * vv[1].z + pv[i].z * vv[2].z + pv[i].w * vv[3].z;
                o[i][3] += pv[i].x * vv[0].w + pv[i].y * vv[1].w + pv[i].z * vv[2].w + pv[i].w * vv[3].w;
            }
        }
    }

    // epilogue: normalize, transpose through smem, coalesced store to (B, D, T)
    __syncthreads();
    float inv[4];
    #pragma unroll
    for (int i = 0; i < 4; i++) inv[i] = 1.0f / l[i];
    #pragma unroll
    for (int i = 0; i < 4; i++)
        #pragma unroll
        for (int j = 0; j < 4; j++)
            Ks[(tx * 4 + j) * 64 + (ty * 4 + i)] = o[i][j] * inv[i];
    __syncthreads();

    const int b = bh >> 4, h = bh & 15;
    float* op = out + ((size_t)b * Dn + h * 64) * Tn + t0;
    #pragma unroll
    for (int u = 0; u < 16; u++) {
        int idx = tid + u * 256;
        int c = idx >> 6, r = idx & 63;
        op[(size_t)c * Tn + r] = Ks[c * 64 + r];
    }
}

extern "C" void kernel_launch(void* const* d_in, const int* in_sizes, int n_in,
                              void* d_out, int out_size) {
    const float* x = (const float*)d_in[0];     // (B, D, T) fp32
    const float* w = (const float*)d_in[1];     // (3, H, D, Dh) fp32
    float* out = (float*)d_out;                 // (B, D, T) fp32

    dim3 g1(Tn / 64, 3 * Bn * Hn);   // (32, 96)
    qkv_proj_kernel<<<g1, 256>>>(x, w);

    dim3 g2(Tn / 64, Bn * Hn);       // (32, 32)
    attn_kernel<<<g2, 256>>>(out);
}